// round 8
// baseline (speedup 1.0000x reference)
#include <cuda_runtime.h>
#include <math.h>

// ---------------- scratch (static, no allocations) ----------------
#define MAXN  65536
#define TABK  4096
#define TABXMAX 16.0f
#define TABB  (TABK / 32)  // table blocks: 8 warps x 4 entries = 32 entries/block
#define PREB  20           // p-precompute blocks

// g_C4 is zero-initialized at module load; node_out re-zeroes it after reading,
// so it is zero at the start of EVERY kernel_launch invocation (no memset pass).
__device__ float4 g_C4[MAXN * 30];   // C[n][a(10)][3 float4]: 9 coeffs + count in slot2.y
__device__ float4 g_pa[MAXN];        // packed (pos.xyz, A-as-bits)
__device__ float4 g_tab[TABK];       // gates(length) table, PATH_NORM folded
__device__ float  g_P[4800];         // P[l(3)][a_dst(10)][a_src(10)][w(16)]

__device__ __forceinline__ float silu_f(float x) {
    return x / (1.0f + __expf(-x));
}

struct TableSmem {
    float sW1[16 * 64];
    float sW2[64 * 64];
    float sW3[3 * 64];
    float sB1[64], sB2[64];
    float sG[8][4][64];
};
struct PSmem {
    float hS[10][64];
    float AiS[10][8];
};

// ---------------- prep: table | P | pack pos+A (no zeroing!) ----------------
__global__ void __launch_bounds__(256)
prep_kernel(const float* __restrict__ pos, const int* __restrict__ A,
            const float* __restrict__ embT,
            const float* __restrict__ aw1, const float* __restrict__ ab1,
            const float* __restrict__ aw2, const float* __restrict__ ab2,
            const float* __restrict__ fw1, const float* __restrict__ fb1,
            const float* __restrict__ fw2, const float* __restrict__ fb2,
            const float* __restrict__ fw3, const float* __restrict__ fb3,
            const float* __restrict__ tpw,
            int N)
{
    __shared__ __align__(16) char smem_raw[sizeof(TableSmem)];
    int bid = blockIdx.x;
    int tid = threadIdx.x;

    if (bid < TABB) {
        // -------- gate table: warp computes 4 entries, 32 entries/block --------
        TableSmem& S = *reinterpret_cast<TableSmem*>(smem_raw);
        for (int i = tid; i < 16 * 64; i += 256) S.sW1[i] = fw1[i];
        for (int i = tid; i < 64 * 64; i += 256) S.sW2[i] = fw2[i];
        if (tid < 64) {
            S.sW3[tid]       = fw3[tid * 15 + 0];
            S.sW3[64 + tid]  = fw3[tid * 15 + 3];
            S.sW3[128 + tid] = fw3[tid * 15 + 9];
            S.sB1[tid] = fb1[tid];
            S.sB2[tid] = fb2[tid];
        }
        __syncthreads();

        int warp = tid >> 5, lane = tid & 31;
        int ebase = bid * 32 + warp * 4;

        float ev[4];
#pragma unroll
        for (int m = 0; m < 4; m++) {
            float x = (TABXMAX * (float)(ebase + m)) / (float)(TABK - 1);
            ev[m] = 0.0f;
            if (lane < 16) {
                const float step = 5.0f / 17.0f;
                float v = 5.0f * (float)(lane + 1) / 17.0f;
                float d = (x - v) / step;
                ev[m] = __expf(-d * d) * (4.0f / 1.12f);
            }
        }

        float a0[4], a1[4];
#pragma unroll
        for (int m = 0; m < 4; m++) { a0[m] = S.sB1[lane]; a1[m] = S.sB1[lane + 32]; }
#pragma unroll
        for (int k = 0; k < 16; k++) {
            float wl = S.sW1[k * 64 + lane];
            float wh = S.sW1[k * 64 + lane + 32];
#pragma unroll
            for (int m = 0; m < 4; m++) {
                float e = __shfl_sync(0xffffffffu, ev[m], k);
                a0[m] += e * wl;
                a1[m] += e * wh;
            }
        }
#pragma unroll
        for (int m = 0; m < 4; m++) {
            S.sG[warp][m][lane]      = silu_f(a0[m]);
            S.sG[warp][m][lane + 32] = silu_f(a1[m]);
        }
        __syncwarp();

        float b0[4], b1[4];
#pragma unroll
        for (int m = 0; m < 4; m++) { b0[m] = S.sB2[lane]; b1[m] = S.sB2[lane + 32]; }
#pragma unroll
        for (int k = 0; k < 64; k++) {
            float wl = S.sW2[k * 64 + lane];
            float wh = S.sW2[k * 64 + lane + 32];
#pragma unroll
            for (int m = 0; m < 4; m++) {
                float g = S.sG[warp][m][k];
                b0[m] += g * wl;
                b1[m] += g * wh;
            }
        }

        const float PN = 0.125f;
        float B0 = __ldg(fb3 + 0), B3 = __ldg(fb3 + 3), B9 = __ldg(fb3 + 9);
#pragma unroll
        for (int m = 0; m < 4; m++) {
            float h0 = silu_f(b0[m]), h1 = silu_f(b1[m]);
            float pa = h0 * S.sW3[lane]       + h1 * S.sW3[lane + 32];
            float pb = h0 * S.sW3[64 + lane]  + h1 * S.sW3[64 + lane + 32];
            float pc = h0 * S.sW3[128 + lane] + h1 * S.sW3[128 + lane + 32];
#pragma unroll
            for (int off = 16; off > 0; off >>= 1) {
                pa += __shfl_xor_sync(0xffffffffu, pa, off);
                pb += __shfl_xor_sync(0xffffffffu, pb, off);
                pc += __shfl_xor_sync(0xffffffffu, pc, off);
            }
            if (lane == 0)
                g_tab[ebase + m] = make_float4((pa + B0) * PN, (pb + B3) * PN,
                                               (pc + B9) * PN, 0.0f);
        }
        return;
    }

    if (bid < TABB + PREB) {
        // -------- P precompute (PREB blocks x 240 entries) --------
        PSmem& S = *reinterpret_cast<PSmem*>(smem_raw);
        for (int idx = tid; idx < 640; idx += 256) {
            int a = idx >> 6, j = idx & 63;
            float acc = ab1[j];
#pragma unroll
            for (int k = 0; k < 16; k++) acc += embT[a * 16 + k] * aw1[k * 64 + j];
            S.hS[a][j] = silu_f(acc);
        }
        __syncthreads();
        if (tid < 80) {
            int a = tid / 8, m = tid % 8;
            float acc = ab2[m];
#pragma unroll
            for (int j = 0; j < 64; j++) acc += S.hS[a][j] * aw2[j * 8 + m];
            S.AiS[a][m] = acc;
        }
        __syncthreads();

        if (tid < 240) {
            int idx = (bid - TABB) * 240 + tid;   // [0, 4800)
            int w  = idx & 15;
            int as = (idx >> 4) % 10;
            int ad = ((idx >> 4) / 10) % 10;
            int l  = idx / 1600;
            int path = (l == 0) ? 0 : (l == 1) ? 3 : 9;
            const float* W = tpw + path * 1024;
            float acc = 0.0f;
#pragma unroll
            for (int u = 0; u < 8; u++) {
                float mu = 0.0f;
#pragma unroll
                for (int v = 0; v < 8; v++)
                    mu += S.AiS[ad][v] * W[(u * 8 + v) * 16 + w];
                acc += S.AiS[as][u] * mu;
            }
            g_P[idx] = acc;
        }
        return;
    }

    // -------- pack pos+A --------
    {
        int n = (bid - TABB - PREB) * 256 + tid;
        if (n < N)
            g_pa[n] = make_float4(pos[3 * n + 0], pos[3 * n + 1], pos[3 * n + 2],
                                  __int_as_float(A[n]));
    }
}

// ---------------- edge scatter ----------------
__global__ void __launch_bounds__(256)
edge_kernel(const int*   __restrict__ esrc,
            const int*   __restrict__ edst,
            const float* __restrict__ shifts,
            const int*   __restrict__ batch,
            const float* __restrict__ cell,
            int E)
{
    int e = blockIdx.x * 256 + threadIdx.x;
    if (e >= E) return;

    int s0 = esrc[e];
    int d0 = edst[e];

    float4 ps = __ldg(&g_pa[s0]);
    float4 pd = __ldg(&g_pa[d0]);

    float dx = pd.x - ps.x;
    float dy = pd.y - ps.y;
    float dz = pd.z - ps.z;

    float shx = shifts[e * 3 + 0];
    float shy = shifts[e * 3 + 1];
    float shz = shifts[e * 3 + 2];
    if (shx != 0.0f || shy != 0.0f || shz != 0.0f) {
        const float* c = cell + (size_t)batch[s0] * 9;
        dx += shx * c[0] + shy * c[3] + shz * c[6];
        dy += shx * c[1] + shy * c[4] + shz * c[7];
        dz += shx * c[2] + shy * c[5] + shz * c[8];
    }

    float len  = sqrtf(dx * dx + dy * dy + dz * dz);
    float rinv = 1.0f / fmaxf(len, 1e-8f);
    float nx = dx * rinv, ny = dy * rinv, nz = dz * rinv;

    float t  = len * ((float)(TABK - 1) / TABXMAX);
    int   i0 = (int)t;
    i0 = i0 < (TABK - 2) ? i0 : (TABK - 2);
    float fr = t - (float)i0;
    float4 ga = __ldg(&g_tab[i0]);
    float4 gb = __ldg(&g_tab[i0 + 1]);
    float G0 = ga.x + fr * (gb.x - ga.x);
    float G1 = ga.y + fr * (gb.y - ga.y);
    float G2 = ga.z + fr * (gb.z - ga.z);

    const float SQ3   = 1.7320508075688772f;
    const float SQ15  = 3.872983346207417f;
    const float SQ5H  = 1.118033988749895f;
    const float SQ15H = 1.9364916731037085f;

    float4 q0 = make_float4(G0,
                            G1 * (SQ3 * nx),
                            G1 * (SQ3 * ny),
                            G1 * (SQ3 * nz));
    float4 q1 = make_float4(G2 * (SQ15 * nx * ny),
                            G2 * (SQ15 * ny * nz),
                            G2 * (SQ5H * (3.0f * nz * nz - 1.0f)),
                            G2 * (SQ15 * nx * nz));
    float4 q2 = make_float4(G2 * (SQ15H * (nx * nx - ny * ny)), 1.0f, 0.0f, 0.0f);

    int a = __float_as_int(ps.w);
    float4* Crow = &g_C4[((size_t)d0 * 10 + a) * 3];
    atomicAdd(&Crow[0], q0);
    atomicAdd(&Crow[1], q1);
    atomicAdd(&Crow[2], q2);
}

// ---------------- node output: 4 threads per node; re-zeroes C after reading ----------------
__global__ void __launch_bounds__(128)
node_out_kernel(float* __restrict__ out, int N)
{
    // Psm[(l*160 + a*16 + w)*10 + at]
    __shared__ float Psm[4800];
    for (int i = threadIdx.x; i < 4800; i += 128) {
        int w  = i & 15;
        int as = (i >> 4) % 10;
        int ad = ((i >> 4) / 10) % 10;
        int l  = i / 1600;
        Psm[(l * 160 + as * 16 + w) * 10 + ad] = g_P[i];
    }
    __syncthreads();

    int t = blockIdx.x * 128 + threadIdx.x;
    int n = t >> 2;
    int q = t & 3;           // w-quarter: w in [4q, 4q+4)
    bool valid = (n < N);

    float acc0[4], acc1[12], acc2[20];
#pragma unroll
    for (int j = 0; j < 4; j++)  acc0[j] = 0.0f;
#pragma unroll
    for (int j = 0; j < 12; j++) acc1[j] = 0.0f;
#pragma unroll
    for (int j = 0; j < 20; j++) acc2[j] = 0.0f;
    float cnt = 0.0f;

    float4* Crow = &g_C4[(size_t)n * 30];   // only dereferenced when valid

    if (valid) {
        int at = __float_as_int(__ldg(&g_pa[n]).w);
        int wb = 4 * q;
#pragma unroll
        for (int a = 0; a < 10; a++) {
            float4 c0 = Crow[a * 3 + 0];
            float4 c1 = Crow[a * 3 + 1];
            float4 c2 = Crow[a * 3 + 2];
            cnt += c2.y;

            const float* P0 = Psm + (a * 16 + wb) * 10 + at;
            const float* P1 = Psm + (160 + a * 16 + wb) * 10 + at;
            const float* P2 = Psm + (320 + a * 16 + wb) * 10 + at;
#pragma unroll
            for (int w = 0; w < 4; w++) {
                float p0 = P0[w * 10];
                float p1 = P1[w * 10];
                float p2 = P2[w * 10];
                acc0[w] += p0 * c0.x;
                acc1[w * 3 + 0] += p1 * c0.y;
                acc1[w * 3 + 1] += p1 * c0.z;
                acc1[w * 3 + 2] += p1 * c0.w;
                acc2[w * 5 + 0] += p2 * c1.x;
                acc2[w * 5 + 1] += p2 * c1.y;
                acc2[w * 5 + 2] += p2 * c1.z;
                acc2[w * 5 + 3] += p2 * c1.w;
                acc2[w * 5 + 4] += p2 * c2.x;
            }
        }
    }

    // All 4 threads of a node have finished READING its C row before anyone
    // zeroes it (quads never straddle warps; no early returns).
    __syncwarp();

    if (valid) {
        // re-zero this node's C slice for the next invocation (8/8/7/7 split)
        const float4 z4 = make_float4(0.f, 0.f, 0.f, 0.f);
        int z0 = (q < 2) ? q * 8 : 16 + (q - 2) * 7;
        int zn = (q < 2) ? 8 : 7;
        for (int j = 0; j < zn; j++) Crow[z0 + j] = z4;

        float inv = 1.0f / fmaxf(cnt, 1.0f);
        float* row = out + (size_t)n * 144;

        // l0: floats [4q, 4q+4)      -> 1 aligned float4
        {
            float4* r4 = (float4*)row + q;
            r4[0] = make_float4(acc0[0]*inv, acc0[1]*inv, acc0[2]*inv, acc0[3]*inv);
        }
        // l1: floats [16+12q, +12)   -> 3 aligned float4
        {
            float4* r4 = (float4*)(row + 16 + 12 * q);
#pragma unroll
            for (int j = 0; j < 3; j++)
                r4[j] = make_float4(acc1[4*j]*inv, acc1[4*j+1]*inv, acc1[4*j+2]*inv, acc1[4*j+3]*inv);
        }
        // l2: floats [64+20q, +20)   -> 5 aligned float4
        {
            float4* r4 = (float4*)(row + 64 + 20 * q);
#pragma unroll
            for (int j = 0; j < 5; j++)
                r4[j] = make_float4(acc2[4*j]*inv, acc2[4*j+1]*inv, acc2[4*j+2]*inv, acc2[4*j+3]*inv);
        }
    }
}

// ---------------- launch ----------------
extern "C" void kernel_launch(void* const* d_in, const int* in_sizes, int n_in,
                              void* d_out, int out_size)
{
    const float* pos    = (const float*)d_in[0];
    const int*   A      = (const int*)  d_in[1];
    const int*   batch  = (const int*)  d_in[2];
    const int*   esrc   = (const int*)  d_in[3];
    const int*   edst   = (const int*)  d_in[4];
    const float* shifts = (const float*)d_in[5];
    const float* cell   = (const float*)d_in[6];
    const float* embT   = (const float*)d_in[7];
    const float* aw1    = (const float*)d_in[8];
    const float* ab1    = (const float*)d_in[9];
    const float* aw2    = (const float*)d_in[10];
    const float* ab2    = (const float*)d_in[11];
    const float* fw1    = (const float*)d_in[12];
    const float* fb1    = (const float*)d_in[13];
    const float* fw2    = (const float*)d_in[14];
    const float* fb2    = (const float*)d_in[15];
    const float* fw3    = (const float*)d_in[16];
    const float* fb3    = (const float*)d_in[17];
    const float* tpw    = (const float*)d_in[18];

    int N = in_sizes[0] / 3;
    int E = in_sizes[3];
    float* out = (float*)d_out;

    int PKB = (N + 255) / 256;
    prep_kernel<<<TABB + PREB + PKB, 256>>>(pos, A, embT, aw1, ab1, aw2, ab2,
                                            fw1, fb1, fw2, fb2, fw3, fb3, tpw, N);
    edge_kernel<<<(E + 255) / 256, 256>>>(esrc, edst, shifts, batch, cell, E);
    node_out_kernel<<<(4 * N + 127) / 128, 128>>>(out, N);
}

// round 9
// speedup vs baseline: 1.1614x; 1.1614x over previous
#include <cuda_runtime.h>
#include <math.h>

// ---------------- scratch (static, no allocations) ----------------
#define MAXN  65536
#define TABK  2048
#define TABXMAX 16.0f
#define TABB  (TABK / 8)   // table blocks: warp per entry, 8 warps/block
#define PREB  20           // p-precompute blocks

__device__ float4 g_C0[MAXN * 10];   // q0 per (n,a): (G0, G1*Y1x, G1*Y1y, G1*Y1z)
__device__ float4 g_C1[MAXN * 10];   // q1 per (n,a): 4 of the l=2 coeffs
__device__ float4 g_C2[MAXN * 5];    // viewed as float2[MAXN*10]: (c8, count)
__device__ float4 g_pa[MAXN];        // packed (pos.xyz, A-as-bits)
__device__ float4 g_tab[TABK];       // gates(length) table, PATH_NORM folded
__device__ float  g_P[4800];         // P[l(3)][a_dst(10)][a_src(10)][w(16)]

__device__ __forceinline__ float silu_f(float x) {
    return x / (1.0f + __expf(-x));
}

struct TableSmem {
    float sW1[16 * 64];
    float sW2[64 * 64];
    float sW3[3 * 64];
    float sB1[64], sB2[64];
    float sG[8][64];
};
struct PSmem {
    float hS[10][64];
    float AiS[10][8];
};

// ---------------- fused prep: zero/pack | table | P ----------------
__global__ void __launch_bounds__(256)
prep_kernel(const float* __restrict__ pos, const int* __restrict__ A,
            const float* __restrict__ embT,
            const float* __restrict__ aw1, const float* __restrict__ ab1,
            const float* __restrict__ aw2, const float* __restrict__ ab2,
            const float* __restrict__ fw1, const float* __restrict__ fb1,
            const float* __restrict__ fw2, const float* __restrict__ fb2,
            const float* __restrict__ fw3, const float* __restrict__ fb3,
            const float* __restrict__ tpw,
            int N, int ZB)
{
    __shared__ __align__(16) char smem_raw[sizeof(TableSmem)];
    int bid = blockIdx.x;
    int tid = threadIdx.x;

    if (bid < ZB) {
        // -------- zero C0/C1/C2, pack pos+A --------
        int i  = bid * 256 + tid;
        int n0 = N * 10;          // C0 f4 count
        int n1 = N * 10;          // C1 f4 count
        int n2 = N * 5;           // C2 f4 count
        const float4 z4 = make_float4(0.f, 0.f, 0.f, 0.f);
        if (i < n0) {
            g_C0[i] = z4;
        } else if (i < n0 + n1) {
            g_C1[i - n0] = z4;
        } else if (i < n0 + n1 + n2) {
            g_C2[i - n0 - n1] = z4;
        } else {
            int n = i - n0 - n1 - n2;
            if (n < N)
                g_pa[n] = make_float4(pos[3 * n + 0], pos[3 * n + 1], pos[3 * n + 2],
                                      __int_as_float(A[n]));
        }
        return;
    }

    if (bid < ZB + TABB) {
        // -------- gate table, warp per entry --------
        TableSmem& S = *reinterpret_cast<TableSmem*>(smem_raw);
        for (int i = tid; i < 16 * 64; i += 256) S.sW1[i] = fw1[i];
        for (int i = tid; i < 64 * 64; i += 256) S.sW2[i] = fw2[i];
        if (tid < 64) {
            S.sW3[tid]       = fw3[tid * 15 + 0];
            S.sW3[64 + tid]  = fw3[tid * 15 + 3];
            S.sW3[128 + tid] = fw3[tid * 15 + 9];
            S.sB1[tid] = fb1[tid];
            S.sB2[tid] = fb2[tid];
        }
        __syncthreads();

        int warp = tid >> 5, lane = tid & 31;
        int entry = (bid - ZB) * 8 + warp;
        float x = (TABXMAX * (float)entry) / (float)(TABK - 1);

        float ev = 0.0f;
        if (lane < 16) {
            const float step = 5.0f / 17.0f;
            float v = 5.0f * (float)(lane + 1) / 17.0f;
            float d = (x - v) / step;
            ev = __expf(-d * d) * (4.0f / 1.12f);
        }

        float a0 = S.sB1[lane], a1 = S.sB1[lane + 32];
#pragma unroll
        for (int k = 0; k < 16; k++) {
            float e = __shfl_sync(0xffffffffu, ev, k);
            a0 += e * S.sW1[k * 64 + lane];
            a1 += e * S.sW1[k * 64 + lane + 32];
        }
        S.sG[warp][lane]      = silu_f(a0);
        S.sG[warp][lane + 32] = silu_f(a1);
        __syncwarp();

        float b0 = S.sB2[lane], b1 = S.sB2[lane + 32];
#pragma unroll
        for (int k = 0; k < 64; k++) {
            float g = S.sG[warp][k];
            b0 += g * S.sW2[k * 64 + lane];
            b1 += g * S.sW2[k * 64 + lane + 32];
        }
        float h0 = silu_f(b0), h1 = silu_f(b1);

        float pa = h0 * S.sW3[lane]       + h1 * S.sW3[lane + 32];
        float pb = h0 * S.sW3[64 + lane]  + h1 * S.sW3[64 + lane + 32];
        float pc = h0 * S.sW3[128 + lane] + h1 * S.sW3[128 + lane + 32];
#pragma unroll
        for (int off = 16; off > 0; off >>= 1) {
            pa += __shfl_xor_sync(0xffffffffu, pa, off);
            pb += __shfl_xor_sync(0xffffffffu, pb, off);
            pc += __shfl_xor_sync(0xffffffffu, pc, off);
        }
        if (lane == 0) {
            const float PN = 0.125f;
            g_tab[entry] = make_float4((pa + __ldg(fb3 + 0)) * PN,
                                       (pb + __ldg(fb3 + 3)) * PN,
                                       (pc + __ldg(fb3 + 9)) * PN, 0.0f);
        }
        return;
    }

    // -------- P precompute (PREB blocks x 240 entries) --------
    {
        PSmem& S = *reinterpret_cast<PSmem*>(smem_raw);
        for (int idx = tid; idx < 640; idx += 256) {
            int a = idx >> 6, j = idx & 63;
            float acc = ab1[j];
#pragma unroll
            for (int k = 0; k < 16; k++) acc += embT[a * 16 + k] * aw1[k * 64 + j];
            S.hS[a][j] = silu_f(acc);
        }
        __syncthreads();
        if (tid < 80) {
            int a = tid / 8, m = tid % 8;
            float acc = ab2[m];
#pragma unroll
            for (int j = 0; j < 64; j++) acc += S.hS[a][j] * aw2[j * 8 + m];
            S.AiS[a][m] = acc;
        }
        __syncthreads();

        if (tid < 240) {
            int idx = (bid - ZB - TABB) * 240 + tid;   // [0, 4800)
            int w  = idx & 15;
            int as = (idx >> 4) % 10;
            int ad = ((idx >> 4) / 10) % 10;
            int l  = idx / 1600;
            int path = (l == 0) ? 0 : (l == 1) ? 3 : 9;
            const float* W = tpw + path * 1024;
            float acc = 0.0f;
#pragma unroll
            for (int u = 0; u < 8; u++) {
                float mu = 0.0f;
#pragma unroll
                for (int v = 0; v < 8; v++)
                    mu += S.AiS[ad][v] * W[(u * 8 + v) * 16 + w];
                acc += S.AiS[as][u] * mu;
            }
            g_P[idx] = acc;
        }
    }
}

// ---------------- edge scatter: 10 atomic lanes per edge ----------------
__global__ void __launch_bounds__(256)
edge_kernel(const int*   __restrict__ esrc,
            const int*   __restrict__ edst,
            const float* __restrict__ shifts,
            const int*   __restrict__ batch,
            const float* __restrict__ cell,
            int E)
{
    int e = blockIdx.x * 256 + threadIdx.x;
    if (e >= E) return;

    int s0 = esrc[e];
    int d0 = edst[e];

    float4 ps = __ldg(&g_pa[s0]);
    float4 pd = __ldg(&g_pa[d0]);

    float dx = pd.x - ps.x;
    float dy = pd.y - ps.y;
    float dz = pd.z - ps.z;

    float shx = shifts[e * 3 + 0];
    float shy = shifts[e * 3 + 1];
    float shz = shifts[e * 3 + 2];
    if (shx != 0.0f || shy != 0.0f || shz != 0.0f) {
        const float* c = cell + (size_t)batch[s0] * 9;
        dx += shx * c[0] + shy * c[3] + shz * c[6];
        dy += shx * c[1] + shy * c[4] + shz * c[7];
        dz += shx * c[2] + shy * c[5] + shz * c[8];
    }

    float len  = sqrtf(dx * dx + dy * dy + dz * dz);
    float rinv = 1.0f / fmaxf(len, 1e-8f);
    float nx = dx * rinv, ny = dy * rinv, nz = dz * rinv;

    float t  = len * ((float)(TABK - 1) / TABXMAX);
    int   i0 = (int)t;
    i0 = i0 < (TABK - 2) ? i0 : (TABK - 2);
    float fr = t - (float)i0;
    float4 ga = __ldg(&g_tab[i0]);
    float4 gb = __ldg(&g_tab[i0 + 1]);
    float G0 = ga.x + fr * (gb.x - ga.x);
    float G1 = ga.y + fr * (gb.y - ga.y);
    float G2 = ga.z + fr * (gb.z - ga.z);

    const float SQ3   = 1.7320508075688772f;
    const float SQ15  = 3.872983346207417f;
    const float SQ5H  = 1.118033988749895f;
    const float SQ15H = 1.9364916731037085f;

    float4 q0 = make_float4(G0,
                            G1 * (SQ3 * nx),
                            G1 * (SQ3 * ny),
                            G1 * (SQ3 * nz));
    float4 q1 = make_float4(G2 * (SQ15 * nx * ny),
                            G2 * (SQ15 * ny * nz),
                            G2 * (SQ5H * (3.0f * nz * nz - 1.0f)),
                            G2 * (SQ15 * nx * nz));
    float2 q2 = make_float2(G2 * (SQ15H * (nx * nx - ny * ny)), 1.0f);

    int a = __float_as_int(ps.w);
    size_t base = (size_t)d0 * 10 + a;
    atomicAdd(&g_C0[base], q0);
    atomicAdd(&g_C1[base], q1);
    atomicAdd(((float2*)g_C2) + base, q2);
}

// ---------------- node output: 2 threads per node (w-halves), all three l ----------------
__global__ void __launch_bounds__(128)
node_out_kernel(float* __restrict__ out, int N)
{
    // Psm[(l*160 + a*16 + w)*10 + at]
    __shared__ float Psm[4800];
    for (int i = threadIdx.x; i < 4800; i += 128) {
        int w  = i & 15;
        int as = (i >> 4) % 10;
        int ad = ((i >> 4) / 10) % 10;
        int l  = i / 1600;
        Psm[(l * 160 + as * 16 + w) * 10 + ad] = g_P[i];
    }
    __syncthreads();

    int t = blockIdx.x * 128 + threadIdx.x;
    int n = t >> 1;
    int q = t & 1;           // w-half: w in [8q, 8q+8)
    if (n >= N) return;

    int at = __float_as_int(__ldg(&g_pa[n]).w);
    const float4*  Crow0 = g_C0 + (size_t)n * 10;
    const float4*  Crow1 = g_C1 + (size_t)n * 10;
    const float2*  Crow2 = ((const float2*)g_C2) + (size_t)n * 10;
    int wb = 8 * q;

    float acc0[8], acc1[24], acc2[40];
#pragma unroll
    for (int j = 0; j < 8; j++)  acc0[j] = 0.0f;
#pragma unroll
    for (int j = 0; j < 24; j++) acc1[j] = 0.0f;
#pragma unroll
    for (int j = 0; j < 40; j++) acc2[j] = 0.0f;

    float cnt = 0.0f;

#pragma unroll
    for (int a = 0; a < 10; a++) {
        float4 c0 = Crow0[a];
        float4 c1 = Crow1[a];
        float2 c2 = Crow2[a];
        cnt += c2.y;

        const float* P0 = Psm + (a * 16 + wb) * 10 + at;
        const float* P1 = Psm + (160 + a * 16 + wb) * 10 + at;
        const float* P2 = Psm + (320 + a * 16 + wb) * 10 + at;
#pragma unroll
        for (int w = 0; w < 8; w++) {
            float p0 = P0[w * 10];
            float p1 = P1[w * 10];
            float p2 = P2[w * 10];
            acc0[w] += p0 * c0.x;
            acc1[w * 3 + 0] += p1 * c0.y;
            acc1[w * 3 + 1] += p1 * c0.z;
            acc1[w * 3 + 2] += p1 * c0.w;
            acc2[w * 5 + 0] += p2 * c1.x;
            acc2[w * 5 + 1] += p2 * c1.y;
            acc2[w * 5 + 2] += p2 * c1.z;
            acc2[w * 5 + 3] += p2 * c1.w;
            acc2[w * 5 + 4] += p2 * c2.x;
        }
    }

    float inv = 1.0f / fmaxf(cnt, 1.0f);
    float* row = out + (size_t)n * 144;

    // l0: floats [8q, 8q+8)  -> 2 aligned float4
    {
        float4* r4 = (float4*)(row) + 2 * q;
#pragma unroll
        for (int j = 0; j < 2; j++)
            r4[j] = make_float4(acc0[4*j]*inv, acc0[4*j+1]*inv, acc0[4*j+2]*inv, acc0[4*j+3]*inv);
    }
    // l1: floats [16+24q, +24) -> 6 aligned float4
    {
        float4* r4 = (float4*)(row + 16 + 24 * q);
#pragma unroll
        for (int j = 0; j < 6; j++)
            r4[j] = make_float4(acc1[4*j]*inv, acc1[4*j+1]*inv, acc1[4*j+2]*inv, acc1[4*j+3]*inv);
    }
    // l2: floats [64+40q, +40) -> 10 aligned float4
    {
        float4* r4 = (float4*)(row + 64 + 40 * q);
#pragma unroll
        for (int j = 0; j < 10; j++)
            r4[j] = make_float4(acc2[4*j]*inv, acc2[4*j+1]*inv, acc2[4*j+2]*inv, acc2[4*j+3]*inv);
    }
}

// ---------------- launch ----------------
extern "C" void kernel_launch(void* const* d_in, const int* in_sizes, int n_in,
                              void* d_out, int out_size)
{
    const float* pos    = (const float*)d_in[0];
    const int*   A      = (const int*)  d_in[1];
    const int*   batch  = (const int*)  d_in[2];
    const int*   esrc   = (const int*)  d_in[3];
    const int*   edst   = (const int*)  d_in[4];
    const float* shifts = (const float*)d_in[5];
    const float* cell   = (const float*)d_in[6];
    const float* embT   = (const float*)d_in[7];
    const float* aw1    = (const float*)d_in[8];
    const float* ab1    = (const float*)d_in[9];
    const float* aw2    = (const float*)d_in[10];
    const float* ab2    = (const float*)d_in[11];
    const float* fw1    = (const float*)d_in[12];
    const float* fb1    = (const float*)d_in[13];
    const float* fw2    = (const float*)d_in[14];
    const float* fb2    = (const float*)d_in[15];
    const float* fw3    = (const float*)d_in[16];
    const float* fb3    = (const float*)d_in[17];
    const float* tpw    = (const float*)d_in[18];

    int N = in_sizes[0] / 3;
    int E = in_sizes[3];
    float* out = (float*)d_out;

    int ZB = (N * 26 + 255) / 256;   // 25N f4 zero + N pack
    prep_kernel<<<ZB + TABB + PREB, 256>>>(pos, A, embT, aw1, ab1, aw2, ab2,
                                           fw1, fb1, fw2, fb2, fw3, fb3, tpw, N, ZB);
    edge_kernel<<<(E + 255) / 256, 256>>>(esrc, edst, shifts, batch, cell, E);
    node_out_kernel<<<(2 * N + 127) / 128, 128>>>(out, N);
}